// round 3
// baseline (speedup 1.0000x reference)
#include <cuda_runtime.h>

#define N_NODES 100000
#define N_EDGES 1600000
#define IN_DIM  128
#define HID_DIM 64
#define NB_SCAN ((N_NODES + 1023) / 1024)   // 98

// ------------------------- device scratch (no allocs allowed) ---------------
// __align__(16): these arrays are accessed via float4/float2 casts.
__device__ int   d_deg [N_NODES];                       // degree incl. self-loop
__device__ int   d_rs  [N_NODES];                       // CSR row starts (edges only)
__device__ int   d_fill[N_NODES];                       // fill cursors
__device__ int   d_csr [N_EDGES];                       // src ids bucketed by dst
__device__ float d_dinv[N_NODES];                       // 1/sqrt(deg)
__device__ __align__(16) float d_bufA[(size_t)N_NODES * HID_DIM]; // GEMM out (dinv-scaled)
__device__ __align__(16) float d_bufB[(size_t)N_NODES * HID_DIM]; // layer activation
__device__ int   d_part[NB_SCAN];                       // scan partials

// ------------------------- degree / CSR build -------------------------------
__global__ void k_init_deg() {
    int i = blockIdx.x * blockDim.x + threadIdx.x;
    if (i < N_NODES) d_deg[i] = 1;                      // self-loop
}

__global__ void k_count(const int* __restrict__ dst) {
    int e = blockIdx.x * blockDim.x + threadIdx.x;
    if (e < N_EDGES) atomicAdd(&d_deg[dst[e]], 1);
}

__global__ void k_scanA() {
    __shared__ int sm[256];
    int base = blockIdx.x * 1024 + threadIdx.x * 4;
    int s = 0;
#pragma unroll
    for (int j = 0; j < 4; ++j) {
        int idx = base + j;
        if (idx < N_NODES) s += d_deg[idx] - 1;         // edges only
    }
    sm[threadIdx.x] = s;
    __syncthreads();
    for (int off = 128; off; off >>= 1) {
        if (threadIdx.x < off) sm[threadIdx.x] += sm[threadIdx.x + off];
        __syncthreads();
    }
    if (threadIdx.x == 0) d_part[blockIdx.x] = sm[0];
}

__global__ void k_scanB() {
    if (threadIdx.x == 0) {
        int s = 0;
        for (int b = 0; b < NB_SCAN; ++b) { int t = d_part[b]; d_part[b] = s; s += t; }
    }
}

__global__ void k_scanC() {
    __shared__ int sm[256];
    int tid = threadIdx.x;
    int base = blockIdx.x * 1024 + tid * 4;
    int v[4];
    int s = 0;
#pragma unroll
    for (int j = 0; j < 4; ++j) {
        int idx = base + j;
        int e = (idx < N_NODES) ? d_deg[idx] - 1 : 0;
        v[j] = s; s += e;
    }
    sm[tid] = s;
    __syncthreads();
#pragma unroll
    for (int off = 1; off < 256; off <<= 1) {
        int t = (tid >= off) ? sm[tid - off] : 0;
        __syncthreads();
        sm[tid] += t;
        __syncthreads();
    }
    int excl = (tid == 0) ? 0 : sm[tid - 1];
    int off0 = d_part[blockIdx.x] + excl;
#pragma unroll
    for (int j = 0; j < 4; ++j) {
        int idx = base + j;
        if (idx < N_NODES) {
            int r = off0 + v[j];
            d_rs[idx]   = r;
            d_fill[idx] = r;
            d_dinv[idx] = rsqrtf((float)d_deg[idx]);
        }
    }
}

__global__ void k_fill(const int* __restrict__ src,
                       const int* __restrict__ dst) {
    int e = blockIdx.x * blockDim.x + threadIdx.x;
    if (e < N_EDGES) {
        int d = dst[e];
        int p = atomicAdd(&d_fill[d], 1);
        d_csr[p] = src[e];
    }
}

// ------------------------- GEMM: C[r,:] = (A[r,:] @ W) * dinv[r] ------------
// Block tile 128x64, thread tile 8x4, full W resident in smem.
template <int K, bool A_IS_PARAM>
__global__ __launch_bounds__(256) void k_gemm(const float* __restrict__ Aparam,
                                              const float* __restrict__ W) {
    __shared__ __align__(16) float sW[K * 64];
    __shared__ __align__(16) float sA[128][17];         // +1 pad: kill bank conflicts
    const float* A = A_IS_PARAM ? Aparam : (const float*)d_bufB;
    int tid = threadIdx.x;
    for (int i = tid; i < K * 64; i += 256) sW[i] = W[i];

    int r0 = blockIdx.x * 128;
    int tx = tid & 15;                                  // col group: cols tx*4..+3
    int ty = tid >> 4;                                  // row group: rows ty*8..+7
    float acc[8][4];
#pragma unroll
    for (int i = 0; i < 8; ++i)
#pragma unroll
        for (int j = 0; j < 4; ++j) acc[i][j] = 0.f;

    for (int kc = 0; kc < K; kc += 16) {
        __syncthreads();                                // sW ready / sA reuse safe
#pragma unroll
        for (int u = 0; u < 2; ++u) {                   // 512 float4 loads, 2/thread
            int idx = tid * 2 + u;
            int row = idx >> 2;
            int c4  = idx & 3;
            int r   = r0 + row;
            float4 v = make_float4(0.f, 0.f, 0.f, 0.f);
            if (r < N_NODES)
                v = *(const float4*)&A[(size_t)r * K + kc + c4 * 4];
            sA[row][c4 * 4 + 0] = v.x;
            sA[row][c4 * 4 + 1] = v.y;
            sA[row][c4 * 4 + 2] = v.z;
            sA[row][c4 * 4 + 3] = v.w;
        }
        __syncthreads();
#pragma unroll
        for (int k = 0; k < 16; ++k) {
            float4 b = *(const float4*)&sW[(kc + k) * 64 + tx * 4];
            float a[8];
#pragma unroll
            for (int i = 0; i < 8; ++i) a[i] = sA[ty * 8 + i][k];
#pragma unroll
            for (int i = 0; i < 8; ++i) {
                acc[i][0] = fmaf(a[i], b.x, acc[i][0]);
                acc[i][1] = fmaf(a[i], b.y, acc[i][1]);
                acc[i][2] = fmaf(a[i], b.z, acc[i][2]);
                acc[i][3] = fmaf(a[i], b.w, acc[i][3]);
            }
        }
    }
#pragma unroll
    for (int i = 0; i < 8; ++i) {
        int r = r0 + ty * 8 + i;
        if (r < N_NODES) {
            float s = d_dinv[r];
            float4 o = make_float4(acc[i][0] * s, acc[i][1] * s,
                                   acc[i][2] * s, acc[i][3] * s);
            *(float4*)&d_bufA[(size_t)r * 64 + tx * 4] = o;
        }
    }
}

// ------------------------- pull aggregation (warp per node) -----------------
// out[i] = relu(dinv[i] * (sum_{e:dst=i} g[src] + g[i]) + b)
// FINAL: additionally fuse the 64->1 FC + bias via warp reduction.
template <bool FINAL>
__global__ __launch_bounds__(256) void k_aggr(const float* __restrict__ bias,
                                              const float* __restrict__ Wfc,
                                              const float* __restrict__ bfc,
                                              float* __restrict__ outp) {
    int gw = (blockIdx.x * blockDim.x + threadIdx.x) >> 5;
    if (gw >= N_NODES) return;
    int lane = threadIdx.x & 31;
    const float2* gp = (const float2*)d_bufA;           // lane owns dims 2*lane, 2*lane+1

    int start = d_rs[gw];
    int cnt   = d_deg[gw] - 1;

    float2 a0 = gp[(size_t)gw * 32 + lane];             // self-loop term
    float2 a1 = make_float2(0.f, 0.f);
    float2 a2 = make_float2(0.f, 0.f);
    float2 a3 = make_float2(0.f, 0.f);

    int t = 0;
    for (; t + 4 <= cnt; t += 4) {                      // 4-deep for memory parallelism
        int s0 = d_csr[start + t + 0];
        int s1 = d_csr[start + t + 1];
        int s2 = d_csr[start + t + 2];
        int s3 = d_csr[start + t + 3];
        float2 v0 = gp[(size_t)s0 * 32 + lane];
        float2 v1 = gp[(size_t)s1 * 32 + lane];
        float2 v2 = gp[(size_t)s2 * 32 + lane];
        float2 v3 = gp[(size_t)s3 * 32 + lane];
        a0.x += v0.x; a0.y += v0.y;
        a1.x += v1.x; a1.y += v1.y;
        a2.x += v2.x; a2.y += v2.y;
        a3.x += v3.x; a3.y += v3.y;
    }
    for (; t < cnt; ++t) {
        int s = d_csr[start + t];
        float2 v = gp[(size_t)s * 32 + lane];
        a0.x += v.x; a0.y += v.y;
    }

    float di = d_dinv[gw];
    float2 bb = ((const float2*)bias)[lane];
    float h0 = fmaf(di, (a0.x + a1.x) + (a2.x + a3.x), bb.x);
    float h1 = fmaf(di, (a0.y + a1.y) + (a2.y + a3.y), bb.y);
    h0 = fmaxf(h0, 0.f);
    h1 = fmaxf(h1, 0.f);

    if (!FINAL) {
        ((float2*)d_bufB)[(size_t)gw * 32 + lane] = make_float2(h0, h1);
    } else {
        float2 w = ((const float2*)Wfc)[lane];
        float p = h0 * w.x + h1 * w.y;
#pragma unroll
        for (int off = 16; off; off >>= 1)
            p += __shfl_down_sync(0xffffffffu, p, off);
        if (lane == 0) outp[gw] = p + bfc[0];
    }
}

// ------------------------- launch ------------------------------------------
extern "C" void kernel_launch(void* const* d_in, const int* in_sizes, int n_in,
                              void* d_out, int out_size) {
    const float* x    = (const float*)d_in[0];
    const int*   ei   = (const int*)d_in[1];   // JAX x64 disabled: int64 -> int32
    const float* W1   = (const float*)d_in[2];
    const float* b1   = (const float*)d_in[3];
    const float* W2   = (const float*)d_in[4];
    const float* b2   = (const float*)d_in[5];
    const float* Wfc  = (const float*)d_in[6];
    const float* bfc  = (const float*)d_in[7];
    float*       out  = (float*)d_out;

    const int* srcp = ei;              // edge_index[0]
    const int* dstp = ei + N_EDGES;    // edge_index[1]

    const int EB = (N_EDGES + 255) / 256;
    const int GB = (N_NODES + 127) / 128;
    const int AB = (N_NODES * 32 + 255) / 256;   // warp per node, 8 warps/block

    // graph structure (rebuilt every call: deterministic)
    k_init_deg<<<(N_NODES + 255) / 256, 256>>>();
    k_count<<<EB, 256>>>(dstp);
    k_scanA<<<NB_SCAN, 256>>>();
    k_scanB<<<1, 32>>>();
    k_scanC<<<NB_SCAN, 256>>>();
    k_fill<<<EB, 256>>>(srcp, dstp);

    // layer 1
    k_gemm<IN_DIM, true ><<<GB, 256>>>(x, W1);
    k_aggr<false><<<AB, 256>>>(b1, Wfc, bfc, out);
    // layer 2 + fused FC head
    k_gemm<HID_DIM, false><<<GB, 256>>>(x /*unused*/, W2);
    k_aggr<true ><<<AB, 256>>>(b2, Wfc, bfc, out);
}

// round 4
// speedup vs baseline: 1.1009x; 1.1009x over previous
#include <cuda_runtime.h>
#include <mma.h>

using namespace nvcuda;

#define N_NODES 100000
#define N_EDGES 1600000
#define IN_DIM  128
#define HID_DIM 64
#define NB_SCAN ((N_NODES + 1023) / 1024)   // 98

// ------------------------- device scratch (no allocs allowed) ---------------
__device__ int   d_deg [N_NODES];                       // degree incl. self-loop
__device__ int   d_rs  [N_NODES];                       // CSR row starts (edges only)
__device__ int   d_fill[N_NODES];                       // fill cursors
__device__ int   d_csr [N_EDGES];                       // src ids bucketed by dst
__device__ float d_dinv[N_NODES];                       // 1/sqrt(deg)
__device__ __align__(16) float d_bufA[(size_t)N_NODES * HID_DIM]; // GEMM out (dinv-scaled)
__device__ __align__(16) float d_bufB[(size_t)N_NODES * HID_DIM]; // layer activation
__device__ int   d_part[NB_SCAN];                       // scan partials

// ------------------------- degree / CSR build -------------------------------
__global__ void k_init_deg() {
    int i = blockIdx.x * blockDim.x + threadIdx.x;
    if (i < N_NODES) d_deg[i] = 1;                      // self-loop
}

__global__ void k_count(const int* __restrict__ dst) {
    int e = blockIdx.x * blockDim.x + threadIdx.x;
    if (e < N_EDGES) atomicAdd(&d_deg[dst[e]], 1);
}

__global__ void k_scanA() {
    __shared__ int sm[256];
    int base = blockIdx.x * 1024 + threadIdx.x * 4;
    int s = 0;
#pragma unroll
    for (int j = 0; j < 4; ++j) {
        int idx = base + j;
        if (idx < N_NODES) s += d_deg[idx] - 1;         // edges only
    }
    sm[threadIdx.x] = s;
    __syncthreads();
    for (int off = 128; off; off >>= 1) {
        if (threadIdx.x < off) sm[threadIdx.x] += sm[threadIdx.x + off];
        __syncthreads();
    }
    if (threadIdx.x == 0) d_part[blockIdx.x] = sm[0];
}

__global__ void k_scanB() {                             // parallel 98-entry scan
    __shared__ int sm[128];
    int t = threadIdx.x;
    int v = (t < NB_SCAN) ? d_part[t] : 0;
    sm[t] = v;
    __syncthreads();
#pragma unroll
    for (int off = 1; off < 128; off <<= 1) {
        int u = (t >= off) ? sm[t - off] : 0;
        __syncthreads();
        sm[t] += u;
        __syncthreads();
    }
    if (t < NB_SCAN) d_part[t] = sm[t] - v;             // exclusive
}

__global__ void k_scanC() {
    __shared__ int sm[256];
    int tid = threadIdx.x;
    int base = blockIdx.x * 1024 + tid * 4;
    int v[4];
    int s = 0;
#pragma unroll
    for (int j = 0; j < 4; ++j) {
        int idx = base + j;
        int e = (idx < N_NODES) ? d_deg[idx] - 1 : 0;
        v[j] = s; s += e;
    }
    sm[tid] = s;
    __syncthreads();
#pragma unroll
    for (int off = 1; off < 256; off <<= 1) {
        int t = (tid >= off) ? sm[tid - off] : 0;
        __syncthreads();
        sm[tid] += t;
        __syncthreads();
    }
    int excl = (tid == 0) ? 0 : sm[tid - 1];
    int off0 = d_part[blockIdx.x] + excl;
#pragma unroll
    for (int j = 0; j < 4; ++j) {
        int idx = base + j;
        if (idx < N_NODES) {
            int r = off0 + v[j];
            d_rs[idx]   = r;
            d_fill[idx] = r;
            d_dinv[idx] = rsqrtf((float)d_deg[idx]);
        }
    }
}

__global__ void k_fill(const int* __restrict__ src,
                       const int* __restrict__ dst) {
    int e = blockIdx.x * blockDim.x + threadIdx.x;
    if (e < N_EDGES) {
        int d = dst[e];
        int p = atomicAdd(&d_fill[d], 1);
        d_csr[p] = src[e];
    }
}

// ------------------------- TF32 GEMM: C[r,:] = (A[r,:] @ W) * dinv[r] -------
// Block tile 128x64. 8 warps, each owns 16 rows (4x m16n16k8 accum frags).
// K chunked by 32. Flat smem reused: [sW 32x64 | sA 128x40] then [sOut 128x68].
#define SA_LD 40
#define SO_LD 68
#define SW_ELE (32 * 64)
#define SMEM_FLOATS 8704     // max(2048 + 128*40, 128*68) = max(7168, 8704)

template <int K, bool A_IS_PARAM>
__global__ __launch_bounds__(256) void k_gemm_tf32(const float* __restrict__ Aparam,
                                                   const float* __restrict__ W) {
    __shared__ __align__(16) float smem[SMEM_FLOATS];
    float* sW = smem;                                   // 32 x 64
    float* sA = smem + SW_ELE;                          // 128 x SA_LD (40)
    const float* A = A_IS_PARAM ? Aparam : (const float*)d_bufB;

    int tid    = threadIdx.x;
    int warpId = tid >> 5;
    int r0     = blockIdx.x * 128;
    int wrow   = warpId * 16;                           // warp's row offset in tile

    wmma::fragment<wmma::matrix_a, 16, 16, 8, wmma::precision::tf32, wmma::row_major> fa;
    wmma::fragment<wmma::matrix_b, 16, 16, 8, wmma::precision::tf32, wmma::row_major> fb;
    wmma::fragment<wmma::accumulator, 16, 16, 8, float> fc[4];
#pragma unroll
    for (int n = 0; n < 4; ++n) wmma::fill_fragment(fc[n], 0.0f);

    for (int kc = 0; kc < K; kc += 32) {
        // load W chunk: rows kc..kc+31 of [K][64], contiguous 2048 floats
#pragma unroll
        for (int u = 0; u < 2; ++u) {
            int idx = u * 256 + tid;                    // float4 index
            float4 v = *(const float4*)&W[(size_t)kc * 64 + idx * 4];
            *(float4*)&sW[idx * 4] = v;
        }
        // load A chunk: 128 rows x 32 cols, 1024 float4
#pragma unroll
        for (int u = 0; u < 4; ++u) {
            int idx = u * 256 + tid;
            int row = idx >> 3;                         // 8 float4 per row
            int c4  = idx & 7;
            int r   = r0 + row;
            float4 v = make_float4(0.f, 0.f, 0.f, 0.f);
            if (r < N_NODES)
                v = *(const float4*)&A[(size_t)r * K + kc + c4 * 4];
            *(float4*)&sA[row * SA_LD + c4 * 4] = v;
        }
        __syncthreads();
#pragma unroll
        for (int kk = 0; kk < 32; kk += 8) {
            wmma::load_matrix_sync(fa, &sA[wrow * SA_LD + kk], SA_LD);
#pragma unroll
            for (int i = 0; i < fa.num_elements; ++i)
                fa.x[i] = wmma::__float_to_tf32(fa.x[i]);
#pragma unroll
            for (int n = 0; n < 4; ++n) {
                wmma::load_matrix_sync(fb, &sW[kk * 64 + n * 16], 64);
#pragma unroll
                for (int i = 0; i < fb.num_elements; ++i)
                    fb.x[i] = wmma::__float_to_tf32(fb.x[i]);
                wmma::mma_sync(fc[n], fa, fb, fc[n]);
            }
        }
        __syncthreads();                                // before chunk reload
    }

    // epilogue: stage to smem, then dinv-scaled float4 global writes
    float* sOut = smem;                                 // 128 x SO_LD (68)
#pragma unroll
    for (int n = 0; n < 4; ++n)
        wmma::store_matrix_sync(&sOut[wrow * SO_LD + n * 16], fc[n], SO_LD,
                                wmma::mem_row_major);
    __syncthreads();
#pragma unroll
    for (int u = 0; u < 8; ++u) {
        int idx = u * 256 + tid;                        // 2048 float4 total
        int row = idx >> 4;                             // 16 float4 per row
        int c4  = idx & 15;
        int r   = r0 + row;
        if (r < N_NODES) {
            float s = d_dinv[r];
            float4 v = *(float4*)&sOut[row * SO_LD + c4 * 4];
            v.x *= s; v.y *= s; v.z *= s; v.w *= s;
            *(float4*)&d_bufA[(size_t)r * 64 + c4 * 4] = v;
        }
    }
}

// ------------------------- pull aggregation (warp per node) -----------------
// out[i] = relu(dinv[i] * (sum_{e:dst=i} g[src] + g[i]) + b)
// FINAL: additionally fuse the 64->1 FC + bias via warp reduction.
template <bool FINAL>
__global__ __launch_bounds__(256) void k_aggr(const float* __restrict__ bias,
                                              const float* __restrict__ Wfc,
                                              const float* __restrict__ bfc,
                                              float* __restrict__ outp) {
    int gw = (blockIdx.x * blockDim.x + threadIdx.x) >> 5;
    if (gw >= N_NODES) return;
    int lane = threadIdx.x & 31;
    const float2* gp = (const float2*)d_bufA;           // lane owns dims 2*lane, 2*lane+1

    int start = d_rs[gw];
    int cnt   = d_deg[gw] - 1;

    float2 a0 = gp[(size_t)gw * 32 + lane];             // self-loop term
    float2 a1 = make_float2(0.f, 0.f);
    float2 a2 = make_float2(0.f, 0.f);
    float2 a3 = make_float2(0.f, 0.f);

    int t = 0;
    for (; t + 4 <= cnt; t += 4) {                      // 4-deep for memory parallelism
        int s0 = d_csr[start + t + 0];
        int s1 = d_csr[start + t + 1];
        int s2 = d_csr[start + t + 2];
        int s3 = d_csr[start + t + 3];
        float2 v0 = gp[(size_t)s0 * 32 + lane];
        float2 v1 = gp[(size_t)s1 * 32 + lane];
        float2 v2 = gp[(size_t)s2 * 32 + lane];
        float2 v3 = gp[(size_t)s3 * 32 + lane];
        a0.x += v0.x; a0.y += v0.y;
        a1.x += v1.x; a1.y += v1.y;
        a2.x += v2.x; a2.y += v2.y;
        a3.x += v3.x; a3.y += v3.y;
    }
    for (; t < cnt; ++t) {
        int s = d_csr[start + t];
        float2 v = gp[(size_t)s * 32 + lane];
        a0.x += v.x; a0.y += v.y;
    }

    float di = d_dinv[gw];
    float2 bb = ((const float2*)bias)[lane];
    float h0 = fmaf(di, (a0.x + a1.x) + (a2.x + a3.x), bb.x);
    float h1 = fmaf(di, (a0.y + a1.y) + (a2.y + a3.y), bb.y);
    h0 = fmaxf(h0, 0.f);
    h1 = fmaxf(h1, 0.f);

    if (!FINAL) {
        ((float2*)d_bufB)[(size_t)gw * 32 + lane] = make_float2(h0, h1);
    } else {
        float2 w = ((const float2*)Wfc)[lane];
        float p = h0 * w.x + h1 * w.y;
#pragma unroll
        for (int off = 16; off; off >>= 1)
            p += __shfl_down_sync(0xffffffffu, p, off);
        if (lane == 0) outp[gw] = p + bfc[0];
    }
}

// ------------------------- launch ------------------------------------------
extern "C" void kernel_launch(void* const* d_in, const int* in_sizes, int n_in,
                              void* d_out, int out_size) {
    const float* x    = (const float*)d_in[0];
    const int*   ei   = (const int*)d_in[1];   // JAX x64 disabled: int64 -> int32
    const float* W1   = (const float*)d_in[2];
    const float* b1   = (const float*)d_in[3];
    const float* W2   = (const float*)d_in[4];
    const float* b2   = (const float*)d_in[5];
    const float* Wfc  = (const float*)d_in[6];
    const float* bfc  = (const float*)d_in[7];
    float*       out  = (float*)d_out;

    const int* srcp = ei;              // edge_index[0]
    const int* dstp = ei + N_EDGES;    // edge_index[1]

    const int EB = (N_EDGES + 255) / 256;
    const int GB = (N_NODES + 127) / 128;
    const int AB = (N_NODES * 32 + 255) / 256;   // warp per node, 8 warps/block

    // graph structure (rebuilt every call: deterministic)
    k_init_deg<<<(N_NODES + 255) / 256, 256>>>();
    k_count<<<EB, 256>>>(dstp);
    k_scanA<<<NB_SCAN, 256>>>();
    k_scanB<<<1, 128>>>();
    k_scanC<<<NB_SCAN, 256>>>();
    k_fill<<<EB, 256>>>(srcp, dstp);

    // layer 1
    k_gemm_tf32<IN_DIM, true ><<<GB, 256>>>(x, W1);
    k_aggr<false><<<AB, 256>>>(b1, Wfc, bfc, out);
    // layer 2 + fused FC head
    k_gemm_tf32<HID_DIM, false><<<GB, 256>>>(x /*unused*/, W2);
    k_aggr<true ><<<AB, 256>>>(b2, Wfc, bfc, out);
}